// round 12
// baseline (speedup 1.0000x reference)
#include <cuda_runtime.h>

// Sinkhorn distance, N=M=4096, D=2, P=1, eps=0.1, 50 iterations.
// Round-2 structure (proven 830us): persistent kernel, CTA owns 32 rows
// (lane=row, warp=j-chunk), smem-staged opposite vector, packed f32x2 +
// MUFU ex2 inner loop in log2 domain.
// Barrier: distinct-address stamped flags (st.release per CTA + one polling
// warp) instead of single-address atomicAdd (~3500cyc L2 serialization per
// barrier, ~200us over 100 barriers).

#define NN      4096
#define NCTA    128
#define NT      1024
#define NWARP   32
#define RPC     32          // rows (or cols) owned per CTA
#define PPW     64          // float2-pairs per warp per pass
#define ITERS   50

#define SCALEF      14.426950408889634f    // log2(e)/eps
#define INV_SCALEF  0.06931471805599453f   // eps*ln(2)
#define LMU2        (-11.9999409054f)      // log2(1/4096 + 1e-8)

typedef unsigned long long ull;

__device__ __align__(128) unsigned int g_flagU[NCTA];
__device__ __align__(128) unsigned int g_flagV[NCTA];
__device__ __align__(256) float g_u[NN];
__device__ __align__(256) float g_v[NN];
__device__ float g_cost[NCTA];
__device__ unsigned int g_costcnt;

__device__ __forceinline__ float ex2f(float v) {
    float r; asm("ex2.approx.f32 %0, %1;" : "=f"(r) : "f"(v)); return r;
}
__device__ __forceinline__ float lg2f(float v) {
    float r; asm("lg2.approx.f32 %0, %1;" : "=f"(r) : "f"(v)); return r;
}
__device__ __forceinline__ ull fadd2(ull a, ull b) {
    ull r; asm("add.rn.f32x2 %0, %1, %2;" : "=l"(r) : "l"(a), "l"(b)); return r;
}
__device__ __forceinline__ ull pk(float lo, float hi) {
    ull r; asm("mov.b64 %0, {%1, %2};" : "=l"(r) : "f"(lo), "f"(hi)); return r;
}
__device__ __forceinline__ void upk(ull v, float& lo, float& hi) {
    asm("mov.b64 {%0, %1}, %2;" : "=f"(lo), "=f"(hi) : "l"(v));
}
__device__ __forceinline__ unsigned int ld_acq(const unsigned int* p) {
    unsigned int v;
    asm volatile("ld.acquire.gpu.global.u32 %0, [%1];" : "=r"(v) : "l"(p));
    return v;
}
__device__ __forceinline__ void st_rel(unsigned int* p, unsigned int v) {
    asm volatile("st.release.gpu.global.u32 [%0], %1;" :: "l"(p), "r"(v) : "memory");
}

// Distinct-address flag barrier: no atomics, no single-line contention.
// All threads call; warp 0 polls the 128 flags (4 coalesced per lane).
__device__ __forceinline__ void grid_barrier(unsigned int* flags, unsigned int stamp,
                                             int cta, int wid, int lane) {
    __threadfence();
    __syncthreads();
    if (wid == 0) {
        if (lane == 0) st_rel(&flags[cta], stamp);
        for (;;) {
            unsigned int a = ld_acq(&flags[lane]);
            unsigned int b = ld_acq(&flags[lane + 32]);
            unsigned int c = ld_acq(&flags[lane + 64]);
            unsigned int d = ld_acq(&flags[lane + 96]);
            bool done = (a >= stamp) && (b >= stamp) && (c >= stamp) && (d >= stamp);
            if (__all_sync(0xffffffffu, done)) break;
        }
    }
    __syncthreads();
}

__global__ void sk_init_kernel() {
    int t = blockIdx.x * blockDim.x + threadIdx.x;
    if (t < NCTA) { g_flagU[t] = 0; g_flagV[t] = 0; }
    if (t == NCTA) g_costcnt = 0;
    for (int i = t; i < NN; i += gridDim.x * blockDim.x) g_v[i] = 0.f;
}

// acc += 2^{v - |X0-y0| - |X1-y1|} for a point pair (packed f32x2).
__device__ __forceinline__ void sk_step(ull& acc, float4 c, float2 vp, ull X0p, ull X1p) {
    ull d0 = fadd2(X0p, pk(c.x, c.y));
    ull d1 = fadd2(X1p, pk(c.z, c.w));
    float d0l, d0h, d1l, d1h;
    upk(d0, d0l, d0h);
    upk(d1, d1l, d1h);
    float sl = -fabsf(d0l) - fabsf(d1l);
    float sh = -fabsf(d0h) - fabsf(d1h);
    ull arg = fadd2(pk(vp.x, vp.y), pk(sl, sh));
    float al, ah;
    upk(arg, al, ah);
    acc = fadd2(acc, pk(ex2f(al), ex2f(ah)));
}

__global__ void __launch_bounds__(NT, 1)
sk_persist_kernel(const float* __restrict__ x, const float* __restrict__ y,
                  float* __restrict__ out) {
    extern __shared__ float4 smem_raw[];
    float4* sxc = smem_raw;                 // 32KB {-x0a,-x0b,-x1a,-x1b} pair-interleaved
    float4* syc = smem_raw + NN / 2;        // 32KB
    float*  su  = (float*)(smem_raw + NN);  // 16KB
    float*  sv  = su + NN;                  // 16KB
    __shared__ float part[NWARP * 33];
    __shared__ float red[NWARP];

    const int tid  = threadIdx.x;
    const int lane = tid & 31;
    const int wid  = tid >> 5;
    const int cta  = blockIdx.x;
    const int rbase = cta * RPC;

    // Prologue: negated, pre-scaled coords (immutable).
    for (int p = tid; p < NN / 2; p += NT) {
        float4 r = ((const float4*)x)[p];
        sxc[p] = make_float4(-SCALEF * r.x, -SCALEF * r.z, -SCALEF * r.y, -SCALEF * r.w);
        float4 q = ((const float4*)y)[p];
        syc[p] = make_float4(-SCALEF * q.x, -SCALEF * q.z, -SCALEF * q.y, -SCALEF * q.w);
    }
    __syncthreads();

    const int myrow = rbase + lane;
    const float X0 = x[2 * myrow] * SCALEF;
    const float X1 = x[2 * myrow + 1] * SCALEF;
    const float Y0 = y[2 * myrow] * SCALEF;
    const float Y1 = y[2 * myrow + 1] * SCALEF;
    const ull X0p = pk(X0, X0), X1p = pk(X1, X1);
    const ull Y0p = pk(Y0, Y0), Y1p = pk(Y1, Y1);

    for (int it = 0; it < ITERS; ++it) {
        // ===== u pass: u_i = LMU2 - log2( sum_j 2^{v_j - C_ij} ) =====
        ((float4*)sv)[tid] = __ldcg((const float4*)g_v + tid);
        __syncthreads();
        {
            const float4* cb = syc + wid * PPW;
            const float2* vp = (const float2*)sv + wid * PPW;
            ull a0 = 0, a1 = 0, a2 = 0, a3 = 0;
            #pragma unroll 4
            for (int k = 0; k < PPW; k += 4) {
                sk_step(a0, cb[k + 0], vp[k + 0], X0p, X1p);
                sk_step(a1, cb[k + 1], vp[k + 1], X0p, X1p);
                sk_step(a2, cb[k + 2], vp[k + 2], X0p, X1p);
                sk_step(a3, cb[k + 3], vp[k + 3], X0p, X1p);
            }
            ull t = fadd2(fadd2(a0, a1), fadd2(a2, a3));
            float tl, th; upk(t, tl, th);
            part[wid * 33 + lane] = tl + th;
        }
        __syncthreads();
        {   // warp `wid` reduces row rbase+wid (transposed, conflict-free)
            float pv = part[lane * 33 + wid];
            #pragma unroll
            for (int o = 16; o > 0; o >>= 1) pv += __shfl_xor_sync(0xffffffffu, pv, o);
            if (lane == 0) __stcg(&g_u[rbase + wid], LMU2 - lg2f(pv));
        }
        grid_barrier(g_flagU, (unsigned int)(it + 1), cta, wid, lane);

        // ===== v pass: v_j = LMU2 - log2( sum_i 2^{u_i - C_ij} ) =====
        ((float4*)su)[tid] = __ldcg((const float4*)g_u + tid);
        __syncthreads();
        {
            const float4* cb = sxc + wid * PPW;
            const float2* up = (const float2*)su + wid * PPW;
            ull a0 = 0, a1 = 0, a2 = 0, a3 = 0;
            #pragma unroll 4
            for (int k = 0; k < PPW; k += 4) {
                sk_step(a0, cb[k + 0], up[k + 0], Y0p, Y1p);
                sk_step(a1, cb[k + 1], up[k + 1], Y0p, Y1p);
                sk_step(a2, cb[k + 2], up[k + 2], Y0p, Y1p);
                sk_step(a3, cb[k + 3], up[k + 3], Y0p, Y1p);
            }
            ull t = fadd2(fadd2(a0, a1), fadd2(a2, a3));
            float tl, th; upk(t, tl, th);
            part[wid * 33 + lane] = tl + th;
        }
        __syncthreads();
        {
            float pv = part[lane * 33 + wid];
            #pragma unroll
            for (int o = 16; o > 0; o >>= 1) pv += __shfl_xor_sync(0xffffffffu, pv, o);
            if (lane == 0) __stcg(&g_v[rbase + wid], LMU2 - lg2f(pv));
        }
        grid_barrier(g_flagV, (unsigned int)(it + 1), cta, wid, lane);
    }

    // ===== final: pi = 2^{u_i + v_j - C_ij}, C, cost = sum(pi*C) =====
    ((float4*)sv)[tid] = __ldcg((const float4*)g_v + tid);
    ((float4*)su)[tid] = __ldcg((const float4*)g_u + tid);
    __syncthreads();

    const size_t NM = (size_t)NN * NN;
    float* pi_out = out + 1;
    float* c_out  = out + 1 + NM;

    float cacc = 0.f;
    for (int r = 0; r < RPC; ++r) {
        const int i = rbase + r;
        const float Xa = x[2 * i] * SCALEF;
        const float Xb = x[2 * i + 1] * SCALEF;
        const float ui = su[i];
        const size_t off = (size_t)i * NN;
        for (int q = tid; q < NN / 4; q += NT) {
            float4 ca = syc[2 * q];
            float4 cb = syc[2 * q + 1];
            float4 v4 = ((const float4*)sv)[q];
            float ct0 = fabsf(Xa + ca.x) + fabsf(Xb + ca.z);
            float ct1 = fabsf(Xa + ca.y) + fabsf(Xb + ca.w);
            float ct2 = fabsf(Xa + cb.x) + fabsf(Xb + cb.z);
            float ct3 = fabsf(Xa + cb.y) + fabsf(Xb + cb.w);
            float p0 = ex2f(ui + v4.x - ct0);
            float p1 = ex2f(ui + v4.y - ct1);
            float p2 = ex2f(ui + v4.z - ct2);
            float p3 = ex2f(ui + v4.w - ct3);
            float c0 = ct0 * INV_SCALEF, c1 = ct1 * INV_SCALEF;
            float c2 = ct2 * INV_SCALEF, c3 = ct3 * INV_SCALEF;
            const size_t b = off + 4 * (size_t)q;
            pi_out[b + 0] = p0; pi_out[b + 1] = p1; pi_out[b + 2] = p2; pi_out[b + 3] = p3;
            c_out[b + 0]  = c0; c_out[b + 1]  = c1; c_out[b + 2]  = c2; c_out[b + 3]  = c3;
            cacc += p0 * c0 + p1 * c1;
            cacc += p2 * c2 + p3 * c3;
        }
    }
    #pragma unroll
    for (int o = 16; o > 0; o >>= 1) cacc += __shfl_xor_sync(0xffffffffu, cacc, o);
    if (lane == 0) red[wid] = cacc;
    __syncthreads();
    if (wid == 0) {
        float s = red[lane];
        #pragma unroll
        for (int o = 16; o > 0; o >>= 1) s += __shfl_xor_sync(0xffffffffu, s, o);
        if (lane == 0) {
            __stcg(&g_cost[cta], s);
            __threadfence();
            unsigned int old = atomicAdd(&g_costcnt, 1u);
            if (old == NCTA - 1) {          // last CTA: deterministic final sum
                __threadfence();
                float t = 0.f;
                for (int b = 0; b < NCTA; ++b) t += __ldcg(&g_cost[b]);
                out[0] = t;                 // cost ** (1/P), P = 1
            }
        }
    }
}

extern "C" void kernel_launch(void* const* d_in, const int* in_sizes, int n_in,
                              void* d_out, int out_size) {
    (void)in_sizes; (void)n_in; (void)out_size;
    const float* x = (const float*)d_in[0];
    const float* y = (const float*)d_in[1];
    float* out = (float*)d_out;

    const size_t smem = (size_t)NN * sizeof(float4) + 2 * NN * sizeof(float); // 96KB
    cudaFuncSetAttribute(sk_persist_kernel,
                         cudaFuncAttributeMaxDynamicSharedMemorySize, (int)smem);

    sk_init_kernel<<<8, 512>>>();
    sk_persist_kernel<<<NCTA, NT, smem>>>(x, y, out);
}

// round 14
// speedup vs baseline: 2.2546x; 2.2546x over previous
#include <cuda_runtime.h>

// Sinkhorn distance, N=M=4096, D=2, P=1, eps=0.1, 50 iterations.
// Round-2 skeleton (proven 830us): persistent kernel, atomicAdd+volatile-spin
// global barrier, CTA owns 32 rows (lane=row, warp=j-chunk), packed f32x2 +
// MUFU ex2 inner loop in log2 domain.
// Changes vs round 2: (1) warp-local staging of the opposite vector slice
// (no CTA-wide sync before the loop), (2) 2-pair inner steps with one
// LDS.128 v4 load per 2 pairs.

#define NN      4096
#define NCTA    128
#define NT      1024
#define NWARP   32
#define RPC     32          // rows (or cols) owned per CTA
#define PPW     64          // float2-pairs per warp per pass
#define ITERS   50

#define SCALEF      14.426950408889634f    // log2(e)/eps
#define INV_SCALEF  0.06931471805599453f   // eps*ln(2)
#define LMU2        (-11.9999409054f)      // log2(1/4096 + 1e-8)

typedef unsigned long long ull;

__device__ __align__(256) float g_u[NN];
__device__ __align__(256) float g_v[NN];
__device__ float g_cost[NCTA];
__device__ unsigned int g_costcnt;
__device__ unsigned int sk_bar_count;
__device__ volatile unsigned int sk_bar_phase;

__device__ __forceinline__ float ex2f(float v) {
    float r; asm("ex2.approx.f32 %0, %1;" : "=f"(r) : "f"(v)); return r;
}
__device__ __forceinline__ float lg2f(float v) {
    float r; asm("lg2.approx.f32 %0, %1;" : "=f"(r) : "f"(v)); return r;
}
__device__ __forceinline__ ull fadd2(ull a, ull b) {
    ull r; asm("add.rn.f32x2 %0, %1, %2;" : "=l"(r) : "l"(a), "l"(b)); return r;
}
__device__ __forceinline__ ull pk(float lo, float hi) {
    ull r; asm("mov.b64 %0, {%1, %2};" : "=l"(r) : "f"(lo), "f"(hi)); return r;
}
__device__ __forceinline__ void upk(ull v, float& lo, float& hi) {
    asm("mov.b64 {%0, %1}, %2;" : "=f"(lo), "=f"(hi) : "l"(v));
}

// Round-2 proven barrier: atomicAdd arrival, tid0 spins on one volatile word.
__device__ __forceinline__ void grid_barrier(unsigned int target) {
    __threadfence();
    __syncthreads();
    if (threadIdx.x == 0) {
        unsigned int t = atomicAdd(&sk_bar_count, 1u);
        if (t == NCTA - 1) {
            sk_bar_count = 0;
            __threadfence();
            sk_bar_phase = target;
        } else {
            while (sk_bar_phase < target) { }
        }
    }
    __syncthreads();
}

__global__ void sk_init_kernel() {
    int t = blockIdx.x * blockDim.x + threadIdx.x;
    if (t == 0) { sk_bar_count = 0; sk_bar_phase = 0; g_costcnt = 0; }
    for (int i = t; i < NN; i += gridDim.x * blockDim.x) g_v[i] = 0.f;
}

// acc += 2^{v - |X0-y0| - |X1-y1|} for a point pair (packed f32x2).
__device__ __forceinline__ void sk_step(ull& acc, float4 c, float vl, float vh,
                                        ull X0p, ull X1p) {
    ull d0 = fadd2(X0p, pk(c.x, c.y));
    ull d1 = fadd2(X1p, pk(c.z, c.w));
    float d0l, d0h, d1l, d1h;
    upk(d0, d0l, d0h);
    upk(d1, d1l, d1h);
    float sl = -fabsf(d0l) - fabsf(d1l);
    float sh = -fabsf(d0h) - fabsf(d1h);
    ull arg = fadd2(pk(vl, vh), pk(sl, sh));
    float al, ah;
    upk(arg, al, ah);
    acc = fadd2(acc, pk(ex2f(al), ex2f(ah)));
}

// Warp-level pass body: stage own 128-float slice of `gvec`, then sum over it.
// Returns this lane's partial (to be transposed+reduced by caller).
__device__ __forceinline__ float warp_pass(const float4* __restrict__ cb,
                                           float* __restrict__ svec,
                                           const float* __restrict__ gvec,
                                           int wid, int lane, ull X0p, ull X1p) {
    // Stage: warp-local, no CTA sync needed (each warp reads only its slice).
    const int c4 = wid * 32 + lane;
    ((float4*)svec)[c4] = __ldcg(((const float4*)gvec) + c4);
    __syncwarp();

    const float4* vb4 = (const float4*)svec + wid * 32;   // 32 float4 = 64 pairs
    ull a0 = 0, a1 = 0, a2 = 0, a3 = 0;
    #pragma unroll 4
    for (int k = 0; k < 32; k += 2) {
        float4 c0 = cb[2 * k + 0];
        float4 c1 = cb[2 * k + 1];
        float4 v0 = vb4[k];
        sk_step(a0, c0, v0.x, v0.y, X0p, X1p);
        sk_step(a1, c1, v0.z, v0.w, X0p, X1p);
        float4 c2 = cb[2 * k + 2];
        float4 c3 = cb[2 * k + 3];
        float4 v1 = vb4[k + 1];
        sk_step(a2, c2, v1.x, v1.y, X0p, X1p);
        sk_step(a3, c3, v1.z, v1.w, X0p, X1p);
    }
    ull t = fadd2(fadd2(a0, a1), fadd2(a2, a3));
    float tl, th;
    upk(t, tl, th);
    return tl + th;
}

__global__ void __launch_bounds__(NT, 1)
sk_persist_kernel(const float* __restrict__ x, const float* __restrict__ y,
                  float* __restrict__ out) {
    extern __shared__ float4 smem_raw[];
    float4* sxc = smem_raw;                 // 32KB {-x0a,-x0b,-x1a,-x1b} pair-interleaved
    float4* syc = smem_raw + NN / 2;        // 32KB
    float*  su  = (float*)(smem_raw + NN);  // 16KB
    float*  sv  = su + NN;                  // 16KB
    __shared__ float part[NWARP * 33];
    __shared__ float red[NWARP];

    const int tid  = threadIdx.x;
    const int lane = tid & 31;
    const int wid  = tid >> 5;
    const int cta  = blockIdx.x;
    const int rbase = cta * RPC;

    // Prologue: negated, pre-scaled coords (immutable).
    for (int p = tid; p < NN / 2; p += NT) {
        float4 r = ((const float4*)x)[p];
        sxc[p] = make_float4(-SCALEF * r.x, -SCALEF * r.z, -SCALEF * r.y, -SCALEF * r.w);
        float4 q = ((const float4*)y)[p];
        syc[p] = make_float4(-SCALEF * q.x, -SCALEF * q.z, -SCALEF * q.y, -SCALEF * q.w);
    }
    __syncthreads();

    const int myrow = rbase + lane;
    const float X0 = x[2 * myrow] * SCALEF;
    const float X1 = x[2 * myrow + 1] * SCALEF;
    const float Y0 = y[2 * myrow] * SCALEF;
    const float Y1 = y[2 * myrow + 1] * SCALEF;
    const ull X0p = pk(X0, X0), X1p = pk(X1, X1);
    const ull Y0p = pk(Y0, Y0), Y1p = pk(Y1, Y1);

    unsigned int phase = 0;

    for (int it = 0; it < ITERS; ++it) {
        // ===== u pass: u_i = LMU2 - log2( sum_j 2^{v_j - C_ij} ) =====
        {
            float s = warp_pass(syc + wid * PPW, sv, g_v, wid, lane, X0p, X1p);
            part[wid * 33 + lane] = s;
        }
        __syncthreads();
        {   // warp `wid` reduces row rbase+wid (transposed, conflict-free)
            float pv = part[lane * 33 + wid];
            #pragma unroll
            for (int o = 16; o > 0; o >>= 1) pv += __shfl_xor_sync(0xffffffffu, pv, o);
            if (lane == 0) __stcg(&g_u[rbase + wid], LMU2 - lg2f(pv));
        }
        grid_barrier(++phase);

        // ===== v pass: v_j = LMU2 - log2( sum_i 2^{u_i - C_ij} ) =====
        {
            float s = warp_pass(sxc + wid * PPW, su, g_u, wid, lane, Y0p, Y1p);
            part[wid * 33 + lane] = s;
        }
        __syncthreads();
        {
            float pv = part[lane * 33 + wid];
            #pragma unroll
            for (int o = 16; o > 0; o >>= 1) pv += __shfl_xor_sync(0xffffffffu, pv, o);
            if (lane == 0) __stcg(&g_v[rbase + wid], LMU2 - lg2f(pv));
        }
        grid_barrier(++phase);
    }

    // ===== final: pi = 2^{u_i + v_j - C_ij}, C, cost = sum(pi*C) =====
    ((float4*)sv)[tid] = __ldcg((const float4*)g_v + tid);
    ((float4*)su)[tid] = __ldcg((const float4*)g_u + tid);
    __syncthreads();

    const size_t NM = (size_t)NN * NN;
    float* pi_out = out + 1;
    float* c_out  = out + 1 + NM;

    float cacc = 0.f;
    for (int r = 0; r < RPC; ++r) {
        const int i = rbase + r;
        const float Xa = x[2 * i] * SCALEF;
        const float Xb = x[2 * i + 1] * SCALEF;
        const float ui = su[i];
        const size_t off = (size_t)i * NN;
        for (int q = tid; q < NN / 4; q += NT) {
            float4 ca = syc[2 * q];
            float4 cb = syc[2 * q + 1];
            float4 v4 = ((const float4*)sv)[q];
            float ct0 = fabsf(Xa + ca.x) + fabsf(Xb + ca.z);
            float ct1 = fabsf(Xa + ca.y) + fabsf(Xb + ca.w);
            float ct2 = fabsf(Xa + cb.x) + fabsf(Xb + cb.z);
            float ct3 = fabsf(Xa + cb.y) + fabsf(Xb + cb.w);
            float p0 = ex2f(ui + v4.x - ct0);
            float p1 = ex2f(ui + v4.y - ct1);
            float p2 = ex2f(ui + v4.z - ct2);
            float p3 = ex2f(ui + v4.w - ct3);
            float c0 = ct0 * INV_SCALEF, c1 = ct1 * INV_SCALEF;
            float c2 = ct2 * INV_SCALEF, c3 = ct3 * INV_SCALEF;
            const size_t b = off + 4 * (size_t)q;
            pi_out[b + 0] = p0; pi_out[b + 1] = p1; pi_out[b + 2] = p2; pi_out[b + 3] = p3;
            c_out[b + 0]  = c0; c_out[b + 1]  = c1; c_out[b + 2]  = c2; c_out[b + 3]  = c3;
            cacc += p0 * c0 + p1 * c1;
            cacc += p2 * c2 + p3 * c3;
        }
    }
    #pragma unroll
    for (int o = 16; o > 0; o >>= 1) cacc += __shfl_xor_sync(0xffffffffu, cacc, o);
    if (lane == 0) red[wid] = cacc;
    __syncthreads();
    if (wid == 0) {
        float s = red[lane];
        #pragma unroll
        for (int o = 16; o > 0; o >>= 1) s += __shfl_xor_sync(0xffffffffu, s, o);
        if (lane == 0) {
            __stcg(&g_cost[cta], s);
            __threadfence();
            unsigned int old = atomicAdd(&g_costcnt, 1u);
            if (old == NCTA - 1) {          // last CTA: deterministic final sum
                __threadfence();
                float t = 0.f;
                for (int b = 0; b < NCTA; ++b) t += __ldcg(&g_cost[b]);
                out[0] = t;                 // cost ** (1/P), P = 1
            }
        }
    }
}

extern "C" void kernel_launch(void* const* d_in, const int* in_sizes, int n_in,
                              void* d_out, int out_size) {
    (void)in_sizes; (void)n_in; (void)out_size;
    const float* x = (const float*)d_in[0];
    const float* y = (const float*)d_in[1];
    float* out = (float*)d_out;

    const size_t smem = (size_t)NN * sizeof(float4) + 2 * NN * sizeof(float); // 96KB
    cudaFuncSetAttribute(sk_persist_kernel,
                         cudaFuncAttributeMaxDynamicSharedMemorySize, (int)smem);

    sk_init_kernel<<<8, 512>>>();
    sk_persist_kernel<<<NCTA, NT, smem>>>(x, y, out);
}